// round 2
// baseline (speedup 1.0000x reference)
#include <cuda_runtime.h>

#define VOCAB 10000
#define EMB   512
#define HID   1024
#define G3    3072
#define TSEQ  64
#define NB    128
#define NT    512
#define SCORES_SZ (TSEQ * VOCAB)

// Scratch (static __device__ arrays; no allocation allowed)
__device__ float g_gi[2][TSEQ][G3];        // precomputed layer-0 input gates (incl. bih)
__device__ float g_h0[2][TSEQ + 1][HID];   // layer-0 hidden per step, [phase]
__device__ float g_h1[2][TSEQ + 1][HID];   // layer-1 hidden per step, [phase]
__device__ volatile int g_flags[NB];       // grid barrier flags (reset by gi_kernel each launch)

// ---------------------------------------------------------------------------
// Kernel 1: precompute gi = emb[ids] @ Wih0^T + bih0 for enc & dec, plus
// init-state copies and barrier-flag reset (runs before the persistent kernel).
// grid: 192 blocks x 256 threads.  b -> net(2) x stile(8) x rblock(12)
// ---------------------------------------------------------------------------
__global__ void gi_kernel(const int* __restrict__ char_seq,
                          const int* __restrict__ sos,
                          const int* __restrict__ target,
                          const float* __restrict__ emb,
                          const float* __restrict__ eWih0, const float* __restrict__ eBih0,
                          const float* __restrict__ dWih0, const float* __restrict__ dBih0,
                          const float* __restrict__ enc_state) {
    __shared__ float xt[8][EMB];   // 16 KB: 8 input embeddings
    int b = blockIdx.x;
    int net = b / 96;
    int rem = b % 96;
    int stile = rem / 12;
    int rb = rem % 12;

    // load 8 embedding rows for this s-tile
    for (int i = threadIdx.x; i < 8 * EMB; i += 256) {
        int sl = i >> 9;         // /512
        int k  = i & 511;
        int s  = stile * 8 + sl;
        int id = (net == 0) ? char_seq[s] : (s == 0 ? sos[0] : target[s - 1]);
        xt[sl][k] = emb[(size_t)id * EMB + k];
    }
    __syncthreads();

    int r = rb * 256 + threadIdx.x;   // 0..3071
    const float* W = ((net == 0) ? eWih0 : dWih0) + (size_t)r * EMB;
    float acc[8];
#pragma unroll
    for (int s = 0; s < 8; s++) acc[s] = 0.f;

#pragma unroll 2
    for (int k = 0; k < EMB; k += 4) {
        float4 w4 = *(const float4*)(W + k);
#pragma unroll
        for (int s = 0; s < 8; s++) {
            float4 xv = *(const float4*)&xt[s][k];
            acc[s] += w4.x * xv.x + w4.y * xv.y + w4.z * xv.z + w4.w * xv.w;
        }
    }
    float bias = ((net == 0) ? eBih0 : dBih0)[r];
#pragma unroll
    for (int s = 0; s < 8; s++)
        g_gi[net][stile * 8 + s][r] = acc[s] + bias;

    // block 0: init encoder hidden state + reset barrier flags (stream-ordered
    // before the persistent kernel, so this is a safe per-launch reset).
    if (b == 0) {
        for (int i = threadIdx.x; i < 2 * HID; i += 256) {
            if (i < HID) g_h0[0][0][i] = enc_state[i];
            else         g_h1[0][0][i - HID] = enc_state[i];
        }
        if (threadIdx.x < NB) g_flags[threadIdx.x] = 0;
    }
}

// ---------------------------------------------------------------------------
// Persistent recurrence kernel: 128 blocks x 512 threads, one block per SM.
// Per iteration i: cell0 computes h0[i+1] (step i), cell1 computes h1[i]
// (step i-1) — both only need data from before the previous barrier.
// ---------------------------------------------------------------------------
__device__ __forceinline__ float wredux(float v) {
    v += __shfl_xor_sync(0xffffffffu, v, 16);
    v += __shfl_xor_sync(0xffffffffu, v, 8);
    v += __shfl_xor_sync(0xffffffffu, v, 4);
    v += __shfl_xor_sync(0xffffffffu, v, 2);
    v += __shfl_xor_sync(0xffffffffu, v, 1);
    return v;
}

__device__ __forceinline__ void grid_barrier(int epoch) {
    __threadfence();
    __syncthreads();
    if (threadIdx.x == 0) g_flags[blockIdx.x] = epoch;
    if (threadIdx.x < NB) {
        while (g_flags[threadIdx.x] < epoch) { __nanosleep(32); }
    }
    __syncthreads();
}

__device__ __forceinline__ float sigmoidf_(float x) {
    return 1.f / (1.f + expf(-x));
}

__global__ void __launch_bounds__(NT, 1)
rec_kernel(const float* __restrict__ eWhh0, const float* __restrict__ eBhh0,
           const float* __restrict__ eWih1, const float* __restrict__ eBih1,
           const float* __restrict__ eWhh1, const float* __restrict__ eBhh1,
           const float* __restrict__ dWhh0, const float* __restrict__ dBhh0,
           const float* __restrict__ dWih1, const float* __restrict__ dBih1,
           const float* __restrict__ dWhh1, const float* __restrict__ dBhh1,
           float* __restrict__ out) {
    __shared__ float s_x[HID];    // h0_all[i] (cell0 hprev == cell1 input)
    __shared__ float s_h1[HID];   // h1_all[i-1]

    const int tid  = threadIdx.x;
    const int wid  = tid >> 5;
    const int lane = tid & 31;
    const int bid  = blockIdx.x;
    int epoch = 0;

    for (int phase = 0; phase < 2; ++phase) {
        const float* Whh0 = phase ? dWhh0 : eWhh0;
        const float* bhh0 = phase ? dBhh0 : eBhh0;
        const float* Wih1 = phase ? dWih1 : eWih1;
        const float* bih1 = phase ? dBih1 : eBih1;
        const float* Whh1 = phase ? dWhh1 : eWhh1;
        const float* bhh1 = phase ? dBhh1 : eBhh1;

        if (phase == 1) {
            // decoder init = encoder final hidden
            for (int i = bid * NT + tid; i < 2 * HID; i += NB * NT) {
                if (i < HID) g_h0[1][0][i] = g_h0[0][TSEQ][i];
                else         g_h1[1][0][i - HID] = g_h1[0][TSEQ][i - HID];
            }
            grid_barrier(++epoch);
        }

        for (int it = 0; it <= TSEQ; ++it) {
            // stage shared vectors
            for (int i = tid; i < HID; i += NT) s_x[i] = g_h0[phase][it][i];
            if (it >= 1)
                for (int i = tid; i < HID; i += NT) s_h1[i] = g_h1[phase][it - 1][i];
            __syncthreads();

            if (wid < 8) {
                // ---- cell0: layer-0 GRU, step t = it ----
                if (it < TSEQ) {
                    const int j = (bid << 3) + wid;
                    const float* w0 = Whh0 + (size_t)j * HID;
                    const float* w1 = w0 + (size_t)HID * HID;
                    const float* w2 = w1 + (size_t)HID * HID;
                    float ar = 0.f, az = 0.f, an = 0.f;
#pragma unroll 4
                    for (int k = lane * 4; k < HID; k += 128) {
                        float4 h4 = *(const float4*)(s_x + k);
                        float4 a = *(const float4*)(w0 + k);
                        float4 b = *(const float4*)(w1 + k);
                        float4 c = *(const float4*)(w2 + k);
                        ar += a.x * h4.x + a.y * h4.y + a.z * h4.z + a.w * h4.w;
                        az += b.x * h4.x + b.y * h4.y + b.z * h4.z + b.w * h4.w;
                        an += c.x * h4.x + c.y * h4.y + c.z * h4.z + c.w * h4.w;
                    }
                    ar = wredux(ar); az = wredux(az); an = wredux(an);
                    if (lane == 0) {
                        const float* gi = g_gi[phase][it];
                        float gr = gi[j]           + ar + bhh0[j];
                        float gz = gi[HID + j]     + az + bhh0[HID + j];
                        float ghn = an + bhh0[2 * HID + j];
                        float rr = sigmoidf_(gr);
                        float zz = sigmoidf_(gz);
                        float nn = tanhf(gi[2 * HID + j] + rr * ghn);
                        float hv = (1.f - zz) * nn + zz * s_x[j];
                        g_h0[phase][it + 1][j] = hv;
                        if (phase) out[SCORES_SZ + it * 2048 + j] = hv;
                    }
                }
            } else {
                // ---- cell1: layer-1 GRU, step t = it-1 ----
                if (it >= 1) {
                    const int j = (bid << 3) + (wid - 8);
                    const float* wi0 = Wih1 + (size_t)j * HID;
                    const float* wi1 = wi0 + (size_t)HID * HID;
                    const float* wi2 = wi1 + (size_t)HID * HID;
                    const float* wh0 = Whh1 + (size_t)j * HID;
                    const float* wh1 = wh0 + (size_t)HID * HID;
                    const float* wh2 = wh1 + (size_t)HID * HID;
                    float ir = 0.f, iz = 0.f, inn = 0.f;
                    float hr = 0.f, hz = 0.f, hnn = 0.f;
#pragma unroll 2
                    for (int k = lane * 4; k < HID; k += 128) {
                        float4 x4 = *(const float4*)(s_x + k);
                        float4 h4 = *(const float4*)(s_h1 + k);
                        float4 a;
                        a = *(const float4*)(wi0 + k);
                        ir  += a.x * x4.x + a.y * x4.y + a.z * x4.z + a.w * x4.w;
                        a = *(const float4*)(wi1 + k);
                        iz  += a.x * x4.x + a.y * x4.y + a.z * x4.z + a.w * x4.w;
                        a = *(const float4*)(wi2 + k);
                        inn += a.x * x4.x + a.y * x4.y + a.z * x4.z + a.w * x4.w;
                        a = *(const float4*)(wh0 + k);
                        hr  += a.x * h4.x + a.y * h4.y + a.z * h4.z + a.w * h4.w;
                        a = *(const float4*)(wh1 + k);
                        hz  += a.x * h4.x + a.y * h4.y + a.z * h4.z + a.w * h4.w;
                        a = *(const float4*)(wh2 + k);
                        hnn += a.x * h4.x + a.y * h4.y + a.z * h4.z + a.w * h4.w;
                    }
                    ir = wredux(ir); iz = wredux(iz); inn = wredux(inn);
                    hr = wredux(hr); hz = wredux(hz); hnn = wredux(hnn);
                    if (lane == 0) {
                        int t = it - 1;
                        float gr = ir + bih1[j]           + hr + bhh1[j];
                        float gz = iz + bih1[HID + j]     + hz + bhh1[HID + j];
                        float gin = inn + bih1[2 * HID + j];
                        float ghn = hnn + bhh1[2 * HID + j];
                        float rr = sigmoidf_(gr);
                        float zz = sigmoidf_(gz);
                        float nn = tanhf(gin + rr * ghn);
                        float hv = (1.f - zz) * nn + zz * s_h1[j];
                        g_h1[phase][it][j] = hv;
                        if (phase) out[SCORES_SZ + t * 2048 + HID + j] = hv;
                    }
                }
            }
            grid_barrier(++epoch);
        }
    }
}

// ---------------------------------------------------------------------------
// Kernel 3: scores = dec_h1 @ out_W^T + out_b   -> out[0 .. 640000)
// grid (20, 8) x 128 threads; each thread: 4 v's x 8 t's.
// ---------------------------------------------------------------------------
__global__ void scores_kernel(const float* __restrict__ outW,
                              const float* __restrict__ outb,
                              float* __restrict__ out) {
    __shared__ float ht[8][128];
    const int tid = threadIdx.x;
    const int vbase = blockIdx.x * 512 + tid;    // + i*128
    const int t0 = blockIdx.y * 8;

    int v[4];
    const float* w[4];
#pragma unroll
    for (int i = 0; i < 4; i++) {
        int vi = vbase + i * 128;
        v[i] = vi;
        int vc = (vi < VOCAB) ? vi : (VOCAB - 1);
        w[i] = outW + (size_t)vc * HID;
    }
    float acc[4][8];
#pragma unroll
    for (int i = 0; i < 4; i++)
#pragma unroll
        for (int tt = 0; tt < 8; tt++) acc[i][tt] = 0.f;

    for (int kc = 0; kc < HID; kc += 128) {
#pragma unroll
        for (int tt = 0; tt < 8; tt++)
            ht[tt][tid] = g_h1[1][t0 + tt + 1][kc + tid];
        __syncthreads();
#pragma unroll 4
        for (int k = 0; k < 128; k += 4) {
            float4 w4[4];
#pragma unroll
            for (int i = 0; i < 4; i++) w4[i] = *(const float4*)(w[i] + kc + k);
#pragma unroll
            for (int tt = 0; tt < 8; tt++) {
                float4 hv = *(const float4*)&ht[tt][k];
#pragma unroll
                for (int i = 0; i < 4; i++)
                    acc[i][tt] += w4[i].x * hv.x + w4[i].y * hv.y +
                                  w4[i].z * hv.z + w4[i].w * hv.w;
            }
        }
        __syncthreads();
    }
#pragma unroll
    for (int i = 0; i < 4; i++) {
        if (v[i] < VOCAB) {
            float bb = outb[v[i]];
#pragma unroll
            for (int tt = 0; tt < 8; tt++)
                out[(size_t)(t0 + tt) * VOCAB + v[i]] = acc[i][tt] + bb;
        }
    }
}

// ---------------------------------------------------------------------------
extern "C" void kernel_launch(void* const* d_in, const int* in_sizes, int n_in,
                              void* d_out, int out_size) {
    // Locate emb_table by its distinctive size (robust to how many scalar
    // inputs — sos/eos/max_len — the harness materializes).
    int p_emb = -1;
    for (int i = 0; i < n_in; i++) {
        if (in_sizes[i] == VOCAB * EMB) { p_emb = i; break; }
    }
    if (p_emb < 0) p_emb = 6;  // fallback: canonical order

    const int*   char_seq  = (const int*)d_in[0];
    const float* enc_state = (const float*)d_in[1];
    const int*   sos       = (const int*)d_in[2];
    const int*   target    = (const int*)d_in[p_emb - 1];
    const float* emb       = (const float*)d_in[p_emb];
    int wbase = p_emb + 1;
    const float* eWih0 = (const float*)d_in[wbase + 0];
    const float* eWhh0 = (const float*)d_in[wbase + 1];
    const float* eBih0 = (const float*)d_in[wbase + 2];
    const float* eBhh0 = (const float*)d_in[wbase + 3];
    const float* eWih1 = (const float*)d_in[wbase + 4];
    const float* eWhh1 = (const float*)d_in[wbase + 5];
    const float* eBih1 = (const float*)d_in[wbase + 6];
    const float* eBhh1 = (const float*)d_in[wbase + 7];
    const float* dWih0 = (const float*)d_in[wbase + 8];
    const float* dWhh0 = (const float*)d_in[wbase + 9];
    const float* dBih0 = (const float*)d_in[wbase + 10];
    const float* dBhh0 = (const float*)d_in[wbase + 11];
    const float* dWih1 = (const float*)d_in[wbase + 12];
    const float* dWhh1 = (const float*)d_in[wbase + 13];
    const float* dBih1 = (const float*)d_in[wbase + 14];
    const float* dBhh1 = (const float*)d_in[wbase + 15];
    const float* outW  = (const float*)d_in[wbase + 16];
    const float* outb  = (const float*)d_in[wbase + 17];
    float* out = (float*)d_out;

    (void)eWih1; (void)dWih0; (void)out_size;

    gi_kernel<<<192, 256>>>(char_seq, sos, target, emb,
                            eWih0, eBih0, dWih0, dBih0, enc_state);

    rec_kernel<<<NB, NT>>>(eWhh0, eBhh0, eWih1, eBih1, eWhh1, eBhh1,
                           dWhh0, dBhh0, dWih1, dBih1, dWhh1, dBhh1, out);

    dim3 sg(20, 8);
    scores_kernel<<<sg, 128>>>(outW, outb, out);
}

// round 3
// speedup vs baseline: 1.1735x; 1.1735x over previous
#include <cuda_runtime.h>

#define VOCAB 10000
#define EMB   512
#define HID   1024
#define TSEQ  64
#define NB    128
#define NT    512
#define SCORES_SZ (TSEQ * VOCAB)

// Scratch (static __device__ arrays; no allocation allowed)
__device__ float g_h0[2][TSEQ + 1][HID];   // layer-0 hidden per step, [phase]
__device__ float g_h1[2][TSEQ + 1][HID];   // layer-1 hidden per step, [phase]
__device__ int   g_flags[NB];              // grid barrier flags (reset by init_kernel)

// ---------------------------------------------------------------------------
// Kernel 1: init encoder hidden + reset barrier flags (stream-ordered before
// the persistent kernel each launch -> deterministic, graph-safe).
// ---------------------------------------------------------------------------
__global__ void init_kernel(const float* __restrict__ enc_state) {
    int t = threadIdx.x;
    if (t < NB) g_flags[t] = 0;
    for (int i = t; i < 2 * HID; i += 256) {
        if (i < HID) g_h0[0][0][i] = enc_state[i];
        else         g_h1[0][0][i - HID] = enc_state[i];
    }
}

// ---------------------------------------------------------------------------
// Grid barrier: release/acquire, NO __threadfence (avoids CCTL.IVALL L1 flush
// every epoch), NO __nanosleep (poll load latency ~250cyc is natural backoff).
// ---------------------------------------------------------------------------
__device__ __forceinline__ void grid_barrier(int epoch) {
    __syncthreads();
    if (threadIdx.x == 0) {
        asm volatile("st.release.gpu.global.b32 [%0], %1;"
                     :: "l"(&g_flags[blockIdx.x]), "r"(epoch) : "memory");
    }
    if (threadIdx.x < NB) {
        int v;
        do {
            asm volatile("ld.acquire.gpu.global.b32 %0, [%1];"
                         : "=r"(v) : "l"(&g_flags[threadIdx.x]) : "memory");
        } while (v < epoch);
    }
    __syncthreads();
}

__device__ __forceinline__ float wredux(float v) {
    v += __shfl_xor_sync(0xffffffffu, v, 16);
    v += __shfl_xor_sync(0xffffffffu, v, 8);
    v += __shfl_xor_sync(0xffffffffu, v, 4);
    v += __shfl_xor_sync(0xffffffffu, v, 2);
    v += __shfl_xor_sync(0xffffffffu, v, 1);
    return v;
}

__device__ __forceinline__ float sigmoidf_(float x) {
    return 1.f / (1.f + expf(-x));
}

// ---------------------------------------------------------------------------
// Persistent recurrence kernel: 128 blocks x 512 threads.
// Per iteration it: warps 0-7 run layer-0 GRU step it (incl. on-the-fly input
// gates from the staged embedding row); warps 8-15 run layer-1 step it-1.
// Embedding row for step it+1 is register-prefetched during iteration it.
// ---------------------------------------------------------------------------
__global__ void __launch_bounds__(NT, 1)
rec_kernel(const float* __restrict__ eWih0, const float* __restrict__ eBih0,
           const float* __restrict__ eWhh0, const float* __restrict__ eBhh0,
           const float* __restrict__ eWih1, const float* __restrict__ eBih1,
           const float* __restrict__ eWhh1, const float* __restrict__ eBhh1,
           const float* __restrict__ dWih0, const float* __restrict__ dBih0,
           const float* __restrict__ dWhh0, const float* __restrict__ dBhh0,
           const float* __restrict__ dWih1, const float* __restrict__ dBih1,
           const float* __restrict__ dWhh1, const float* __restrict__ dBhh1,
           const int* __restrict__ char_seq,
           const int* __restrict__ sos,
           const int* __restrict__ target,
           const float* __restrict__ emb,
           float* __restrict__ out) {
    __shared__ float s_x[HID];    // h0_all[it] (cell0 hprev == cell1 input)
    __shared__ float s_h1[HID];   // h1_all[it-1]
    __shared__ float s_e[EMB];    // embedding of input token for step it

    const int tid  = threadIdx.x;
    const int wid  = tid >> 5;
    const int lane = tid & 31;
    const int bid  = blockIdx.x;
    const int sos0 = sos[0];
    int epoch = 0;

    for (int phase = 0; phase < 2; ++phase) {
        const float* Wih0 = phase ? dWih0 : eWih0;
        const float* bih0 = phase ? dBih0 : eBih0;
        const float* Whh0 = phase ? dWhh0 : eWhh0;
        const float* bhh0 = phase ? dBhh0 : eBhh0;
        const float* Wih1 = phase ? dWih1 : eWih1;
        const float* bih1 = phase ? dBih1 : eBih1;
        const float* Whh1 = phase ? dWhh1 : eWhh1;
        const float* bhh1 = phase ? dBhh1 : eBhh1;

        if (phase == 1) {
            // decoder init = encoder final hidden
            for (int i = bid * NT + tid; i < 2 * HID; i += NB * NT) {
                if (i < HID) g_h0[1][0][i] = g_h0[0][TSEQ][i];
                else         g_h1[1][0][i - HID] = g_h1[0][TSEQ][i - HID];
            }
            grid_barrier(++epoch);
        }

        // preload embedding row for step 0 of this phase
        int id0 = (phase == 0) ? char_seq[0] : sos0;
        float pf = emb[(size_t)id0 * EMB + tid];

        for (int it = 0; it <= TSEQ; ++it) {
            // stage shared vectors (writes ordered before compute by syncthreads)
            if (it < TSEQ) s_e[tid] = pf;
            for (int i = tid; i < HID; i += NT) s_x[i] = g_h0[phase][it][i];
            if (it >= 1)
                for (int i = tid; i < HID; i += NT) s_h1[i] = g_h1[phase][it - 1][i];
            __syncthreads();

            // prefetch next step's embedding row (consumed at next iter top)
            if (it + 1 < TSEQ) {
                int idn = (phase == 0) ? char_seq[it + 1]
                                       : (it + 1 == 0 ? sos0 : target[it]);
                pf = emb[(size_t)idn * EMB + tid];
            }

            if (wid < 8) {
                // ---- cell0: layer-0 GRU, step t = it (hh + ih dots) ----
                if (it < TSEQ) {
                    const int j = (bid << 3) + wid;
                    const float* w0 = Whh0 + (size_t)j * HID;
                    const float* w1 = w0 + (size_t)HID * HID;
                    const float* w2 = w1 + (size_t)HID * HID;
                    const float* u0 = Wih0 + (size_t)j * EMB;
                    const float* u1 = u0 + (size_t)HID * EMB;
                    const float* u2 = u1 + (size_t)HID * EMB;
                    float ar = 0.f, az = 0.f, an = 0.f, xn = 0.f;
#pragma unroll 4
                    for (int k = lane * 4; k < HID; k += 128) {
                        float4 h4 = *(const float4*)(s_x + k);
                        float4 a = *(const float4*)(w0 + k);
                        float4 b = *(const float4*)(w1 + k);
                        float4 c = *(const float4*)(w2 + k);
                        ar += a.x * h4.x + a.y * h4.y + a.z * h4.z + a.w * h4.w;
                        az += b.x * h4.x + b.y * h4.y + b.z * h4.z + b.w * h4.w;
                        an += c.x * h4.x + c.y * h4.y + c.z * h4.z + c.w * h4.w;
                    }
#pragma unroll 4
                    for (int k = lane * 4; k < EMB; k += 128) {
                        float4 e4 = *(const float4*)(s_e + k);
                        float4 a = *(const float4*)(u0 + k);
                        float4 b = *(const float4*)(u1 + k);
                        float4 c = *(const float4*)(u2 + k);
                        ar += a.x * e4.x + a.y * e4.y + a.z * e4.z + a.w * e4.w;
                        az += b.x * e4.x + b.y * e4.y + b.z * e4.z + b.w * e4.w;
                        xn += c.x * e4.x + c.y * e4.y + c.z * e4.z + c.w * e4.w;
                    }
                    ar = wredux(ar); az = wredux(az);
                    an = wredux(an); xn = wredux(xn);
                    if (lane == 0) {
                        float gr = ar + bih0[j]       + bhh0[j];
                        float gz = az + bih0[HID + j] + bhh0[HID + j];
                        float gin = xn + bih0[2 * HID + j];
                        float ghn = an + bhh0[2 * HID + j];
                        float rr = sigmoidf_(gr);
                        float zz = sigmoidf_(gz);
                        float nn = tanhf(gin + rr * ghn);
                        float hv = (1.f - zz) * nn + zz * s_x[j];
                        g_h0[phase][it + 1][j] = hv;
                        if (phase) out[SCORES_SZ + it * 2048 + j] = hv;
                    }
                }
            } else {
                // ---- cell1: layer-1 GRU, step t = it-1 ----
                if (it >= 1) {
                    const int j = (bid << 3) + (wid - 8);
                    const float* wi0 = Wih1 + (size_t)j * HID;
                    const float* wi1 = wi0 + (size_t)HID * HID;
                    const float* wi2 = wi1 + (size_t)HID * HID;
                    const float* wh0 = Whh1 + (size_t)j * HID;
                    const float* wh1 = wh0 + (size_t)HID * HID;
                    const float* wh2 = wh1 + (size_t)HID * HID;
                    float ir = 0.f, iz = 0.f, inn = 0.f;
                    float hr = 0.f, hz = 0.f, hnn = 0.f;
#pragma unroll 2
                    for (int k = lane * 4; k < HID; k += 128) {
                        float4 x4 = *(const float4*)(s_x + k);
                        float4 h4 = *(const float4*)(s_h1 + k);
                        float4 a;
                        a = *(const float4*)(wi0 + k);
                        ir  += a.x * x4.x + a.y * x4.y + a.z * x4.z + a.w * x4.w;
                        a = *(const float4*)(wi1 + k);
                        iz  += a.x * x4.x + a.y * x4.y + a.z * x4.z + a.w * x4.w;
                        a = *(const float4*)(wi2 + k);
                        inn += a.x * x4.x + a.y * x4.y + a.z * x4.z + a.w * x4.w;
                        a = *(const float4*)(wh0 + k);
                        hr  += a.x * h4.x + a.y * h4.y + a.z * h4.z + a.w * h4.w;
                        a = *(const float4*)(wh1 + k);
                        hz  += a.x * h4.x + a.y * h4.y + a.z * h4.z + a.w * h4.w;
                        a = *(const float4*)(wh2 + k);
                        hnn += a.x * h4.x + a.y * h4.y + a.z * h4.z + a.w * h4.w;
                    }
                    ir = wredux(ir); iz = wredux(iz); inn = wredux(inn);
                    hr = wredux(hr); hz = wredux(hz); hnn = wredux(hnn);
                    if (lane == 0) {
                        int t = it - 1;
                        float gr = ir + bih1[j]           + hr + bhh1[j];
                        float gz = iz + bih1[HID + j]     + hz + bhh1[HID + j];
                        float gin = inn + bih1[2 * HID + j];
                        float ghn = hnn + bhh1[2 * HID + j];
                        float rr = sigmoidf_(gr);
                        float zz = sigmoidf_(gz);
                        float nn = tanhf(gin + rr * ghn);
                        float hv = (1.f - zz) * nn + zz * s_h1[j];
                        g_h1[phase][it][j] = hv;
                        if (phase) out[SCORES_SZ + t * 2048 + HID + j] = hv;
                    }
                }
            }
            grid_barrier(++epoch);
        }
    }
}

// ---------------------------------------------------------------------------
// Kernel 3: scores = dec_h1 @ out_W^T + out_b   -> out[0 .. 640000)
// grid (20, 8) x 128 threads; each thread: 4 v's x 8 t's.
// ---------------------------------------------------------------------------
__global__ void scores_kernel(const float* __restrict__ outW,
                              const float* __restrict__ outb,
                              float* __restrict__ out) {
    __shared__ float ht[8][128];
    const int tid = threadIdx.x;
    const int vbase = blockIdx.x * 512 + tid;    // + i*128
    const int t0 = blockIdx.y * 8;

    int v[4];
    const float* w[4];
#pragma unroll
    for (int i = 0; i < 4; i++) {
        int vi = vbase + i * 128;
        v[i] = vi;
        int vc = (vi < VOCAB) ? vi : (VOCAB - 1);
        w[i] = outW + (size_t)vc * HID;
    }
    float acc[4][8];
#pragma unroll
    for (int i = 0; i < 4; i++)
#pragma unroll
        for (int tt = 0; tt < 8; tt++) acc[i][tt] = 0.f;

    for (int kc = 0; kc < HID; kc += 128) {
#pragma unroll
        for (int tt = 0; tt < 8; tt++)
            ht[tt][tid] = g_h1[1][t0 + tt + 1][kc + tid];
        __syncthreads();
#pragma unroll 4
        for (int k = 0; k < 128; k += 4) {
            float4 w4[4];
#pragma unroll
            for (int i = 0; i < 4; i++) w4[i] = *(const float4*)(w[i] + kc + k);
#pragma unroll
            for (int tt = 0; tt < 8; tt++) {
                float4 hv = *(const float4*)&ht[tt][k];
#pragma unroll
                for (int i = 0; i < 4; i++)
                    acc[i][tt] += w4[i].x * hv.x + w4[i].y * hv.y +
                                  w4[i].z * hv.z + w4[i].w * hv.w;
            }
        }
        __syncthreads();
    }
#pragma unroll
    for (int i = 0; i < 4; i++) {
        if (v[i] < VOCAB) {
            float bb = outb[v[i]];
#pragma unroll
            for (int tt = 0; tt < 8; tt++)
                out[(size_t)(t0 + tt) * VOCAB + v[i]] = acc[i][tt] + bb;
        }
    }
}

// ---------------------------------------------------------------------------
extern "C" void kernel_launch(void* const* d_in, const int* in_sizes, int n_in,
                              void* d_out, int out_size) {
    // Locate emb_table by its distinctive size (robust to how many scalar
    // inputs — sos/eos/max_len — the harness materializes).
    int p_emb = -1;
    for (int i = 0; i < n_in; i++) {
        if (in_sizes[i] == VOCAB * EMB) { p_emb = i; break; }
    }
    if (p_emb < 0) p_emb = 6;  // fallback: canonical order

    const int*   char_seq  = (const int*)d_in[0];
    const float* enc_state = (const float*)d_in[1];
    const int*   sos       = (const int*)d_in[2];
    const int*   target    = (const int*)d_in[p_emb - 1];
    const float* emb       = (const float*)d_in[p_emb];
    int wbase = p_emb + 1;
    const float* eWih0 = (const float*)d_in[wbase + 0];
    const float* eWhh0 = (const float*)d_in[wbase + 1];
    const float* eBih0 = (const float*)d_in[wbase + 2];
    const float* eBhh0 = (const float*)d_in[wbase + 3];
    const float* eWih1 = (const float*)d_in[wbase + 4];
    const float* eWhh1 = (const float*)d_in[wbase + 5];
    const float* eBih1 = (const float*)d_in[wbase + 6];
    const float* eBhh1 = (const float*)d_in[wbase + 7];
    const float* dWih0 = (const float*)d_in[wbase + 8];
    const float* dWhh0 = (const float*)d_in[wbase + 9];
    const float* dBih0 = (const float*)d_in[wbase + 10];
    const float* dBhh0 = (const float*)d_in[wbase + 11];
    const float* dWih1 = (const float*)d_in[wbase + 12];
    const float* dWhh1 = (const float*)d_in[wbase + 13];
    const float* dBih1 = (const float*)d_in[wbase + 14];
    const float* dBhh1 = (const float*)d_in[wbase + 15];
    const float* outW  = (const float*)d_in[wbase + 16];
    const float* outb  = (const float*)d_in[wbase + 17];
    float* out = (float*)d_out;
    (void)out_size;

    init_kernel<<<1, 256>>>(enc_state);

    rec_kernel<<<NB, NT>>>(eWih0, eBih0, eWhh0, eBhh0,
                           eWih1, eBih1, eWhh1, eBhh1,
                           dWih0, dBih0, dWhh0, dBhh0,
                           dWih1, dBih1, dWhh1, dBhh1,
                           char_seq, sos, target, emb, out);

    dim3 sg(20, 8);
    scores_kernel<<<sg, 128>>>(outW, outb, out);
}

// round 6
// speedup vs baseline: 2.1785x; 1.8564x over previous
#include <cuda_runtime.h>

#define VOCAB 10000
#define EMB   512
#define HID   1024
#define TSEQ  64
#define NB    128
#define NT    512
#define SCORES_SZ (TSEQ * VOCAB)

// dynamic smem layout (floats):
//  [0 .. 49152)        cell1 weights: 8 rows x 6 segs x 1024
//  [49152 .. 50176)    s_x   (HID)
//  [50176 .. 51200)    s_h1  (HID)
//  [51200 .. 51712)    s_e   (EMB)
#define SW1_F   (8 * 6 * 1024)
#define SMEM_FLOATS (SW1_F + HID + HID + EMB)
#define SMEM_BYTES  (SMEM_FLOATS * 4)

// Scratch (static __device__ arrays; no allocation allowed)
__device__ float g_h0[2][TSEQ + 1][HID];   // layer-0 hidden per step, [phase]
__device__ float g_h1[2][TSEQ + 1][HID];   // layer-1 hidden per step, [phase]
__device__ int   g_count;                  // barrier arrival counter (reset each launch)

// ---------------------------------------------------------------------------
__global__ void init_kernel(const float* __restrict__ enc_state) {
    int t = threadIdx.x;
    if (t == 0) g_count = 0;
    for (int i = t; i < 2 * HID; i += 256) {
        if (i < HID) g_h0[0][0][i] = enc_state[i];
        else         g_h1[0][0][i - HID] = enc_state[i];
    }
}

// ---------------------------------------------------------------------------
// Grid barrier: single counter; one red.release per block; only thread 0 polls.
// ---------------------------------------------------------------------------
__device__ __forceinline__ void grid_barrier(int epoch) {
    __syncthreads();
    if (threadIdx.x == 0) {
        asm volatile("red.release.gpu.global.add.s32 [%0], 1;"
                     :: "l"(&g_count) : "memory");
        int target = epoch * NB;
        int v;
        do {
            asm volatile("ld.acquire.gpu.global.b32 %0, [%1];"
                         : "=r"(v) : "l"(&g_count) : "memory");
        } while (v < target);
    }
    __syncthreads();
}

__device__ __forceinline__ float wredux(float v) {
    v += __shfl_xor_sync(0xffffffffu, v, 16);
    v += __shfl_xor_sync(0xffffffffu, v, 8);
    v += __shfl_xor_sync(0xffffffffu, v, 4);
    v += __shfl_xor_sync(0xffffffffu, v, 2);
    v += __shfl_xor_sync(0xffffffffu, v, 1);
    return v;
}

__device__ __forceinline__ float sigmoidf_(float x) {
    return 1.f / (1.f + expf(-x));
}

// ---------------------------------------------------------------------------
// Persistent recurrence kernel: 128 blocks x 512 threads.
// warps 0-7: layer-0 GRU step it (weights stream from L2);
// warps 8-15: layer-1 GRU step it-1 (weights SMEM-resident, loaded per phase).
// ---------------------------------------------------------------------------
__global__ void __launch_bounds__(NT, 1)
rec_kernel(const float* __restrict__ eWih0, const float* __restrict__ eBih0,
           const float* __restrict__ eWhh0, const float* __restrict__ eBhh0,
           const float* __restrict__ eWih1, const float* __restrict__ eBih1,
           const float* __restrict__ eWhh1, const float* __restrict__ eBhh1,
           const float* __restrict__ dWih0, const float* __restrict__ dBih0,
           const float* __restrict__ dWhh0, const float* __restrict__ dBhh0,
           const float* __restrict__ dWih1, const float* __restrict__ dBih1,
           const float* __restrict__ dWhh1, const float* __restrict__ dBhh1,
           const int* __restrict__ char_seq,
           const int* __restrict__ sos,
           const int* __restrict__ target,
           const float* __restrict__ emb,
           float* __restrict__ out) {
    extern __shared__ float smem[];
    float* s_w1 = smem;                    // [8][6][1024]
    float* s_x  = smem + SW1_F;            // [HID]
    float* s_h1 = s_x + HID;               // [HID]
    float* s_e  = s_h1 + HID;              // [EMB]

    const int tid  = threadIdx.x;
    const int wid  = tid >> 5;
    const int lane = tid & 31;
    const int bid  = blockIdx.x;
    const int sos0 = sos[0];
    int epoch = 0;

    for (int phase = 0; phase < 2; ++phase) {
        const float* Wih0 = phase ? dWih0 : eWih0;
        const float* bih0 = phase ? dBih0 : eBih0;
        const float* Whh0 = phase ? dWhh0 : eWhh0;
        const float* bhh0 = phase ? dBhh0 : eBhh0;
        const float* Wih1 = phase ? dWih1 : eWih1;
        const float* bih1 = phase ? dBih1 : eBih1;
        const float* Whh1 = phase ? dWhh1 : eWhh1;
        const float* bhh1 = phase ? dBhh1 : eBhh1;

        if (phase == 1) {
            // decoder init = encoder final hidden
            for (int i = bid * NT + tid; i < 2 * HID; i += NB * NT) {
                if (i < HID) g_h0[1][0][i] = g_h0[0][TSEQ][i];
                else         g_h1[1][0][i - HID] = g_h1[0][TSEQ][i - HID];
            }
            grid_barrier(++epoch);
        }

        // ---- load cell1 weights for this phase into smem ----
        // s_w1[row][seg][k]: seg 0..2 = Wih1 gates, 3..5 = Whh1 gates; row = local row
        {
            float4* dst = (float4*)s_w1;
            for (int idx = tid; idx < 8 * 6 * 256; idx += NT) {
                int row = idx / (6 * 256);
                int rem = idx % (6 * 256);
                int seg = rem / 256;
                int k4  = rem % 256;
                int j = (bid << 3) + row;          // global output row
                const float* src = (seg < 3)
                    ? (Wih1 + ((size_t)seg * HID + j) * HID)
                    : (Whh1 + ((size_t)(seg - 3) * HID + j) * HID);
                dst[idx] = *(const float4*)(src + k4 * 4);
            }
        }

        // preload embedding row for step 0 of this phase
        int id0 = (phase == 0) ? char_seq[0] : sos0;
        float pf = emb[(size_t)id0 * EMB + tid];

        for (int it = 0; it <= TSEQ; ++it) {
            // stage shared vectors (ordered before compute by __syncthreads)
            if (it < TSEQ) s_e[tid] = pf;
            for (int i = tid; i < HID; i += NT) s_x[i] = g_h0[phase][it][i];
            if (it >= 1)
                for (int i = tid; i < HID; i += NT) s_h1[i] = g_h1[phase][it - 1][i];
            __syncthreads();

            // prefetch next step's embedding row
            if (it + 1 < TSEQ) {
                int idn = (phase == 0) ? char_seq[it + 1] : target[it];
                pf = emb[(size_t)idn * EMB + tid];
            }

            if (wid < 8) {
                // ---- cell0: layer-0 GRU, step t = it (L2-streamed weights) ----
                if (it < TSEQ) {
                    const int j = (bid << 3) + wid;
                    const float* w0 = Whh0 + (size_t)j * HID;
                    const float* w1 = w0 + (size_t)HID * HID;
                    const float* w2 = w1 + (size_t)HID * HID;
                    const float* u0 = Wih0 + (size_t)j * EMB;
                    const float* u1 = u0 + (size_t)HID * EMB;
                    const float* u2 = u1 + (size_t)HID * EMB;
                    float ar = 0.f, az = 0.f, an = 0.f, xn = 0.f;
#pragma unroll 4
                    for (int k = lane * 4; k < HID; k += 128) {
                        float4 h4 = *(const float4*)(s_x + k);
                        float4 a = *(const float4*)(w0 + k);
                        float4 b = *(const float4*)(w1 + k);
                        float4 c = *(const float4*)(w2 + k);
                        ar += a.x * h4.x + a.y * h4.y + a.z * h4.z + a.w * h4.w;
                        az += b.x * h4.x + b.y * h4.y + b.z * h4.z + b.w * h4.w;
                        an += c.x * h4.x + c.y * h4.y + c.z * h4.z + c.w * h4.w;
                    }
#pragma unroll 4
                    for (int k = lane * 4; k < EMB; k += 128) {
                        float4 e4 = *(const float4*)(s_e + k);
                        float4 a = *(const float4*)(u0 + k);
                        float4 b = *(const float4*)(u1 + k);
                        float4 c = *(const float4*)(u2 + k);
                        ar += a.x * e4.x + a.y * e4.y + a.z * e4.z + a.w * e4.w;
                        az += b.x * e4.x + b.y * e4.y + b.z * e4.z + b.w * e4.w;
                        xn += c.x * e4.x + c.y * e4.y + c.z * e4.z + c.w * e4.w;
                    }
                    ar = wredux(ar); az = wredux(az);
                    an = wredux(an); xn = wredux(xn);
                    if (lane == 0) {
                        float gr = ar + bih0[j]       + bhh0[j];
                        float gz = az + bih0[HID + j] + bhh0[HID + j];
                        float gin = xn + bih0[2 * HID + j];
                        float ghn = an + bhh0[2 * HID + j];
                        float rr = sigmoidf_(gr);
                        float zz = sigmoidf_(gz);
                        float nn = tanhf(gin + rr * ghn);
                        float hv = (1.f - zz) * nn + zz * s_x[j];
                        g_h0[phase][it + 1][j] = hv;
                        if (phase) out[SCORES_SZ + it * 2048 + j] = hv;
                    }
                }
            } else {
                // ---- cell1: layer-1 GRU, step t = it-1 (SMEM weights) ----
                if (it >= 1) {
                    const int row = wid - 8;
                    const int j = (bid << 3) + row;
                    const float* sw = s_w1 + (size_t)row * 6 * 1024;
                    const float* wi0 = sw;
                    const float* wi1 = sw + 1024;
                    const float* wi2 = sw + 2048;
                    const float* wh0 = sw + 3072;
                    const float* wh1 = sw + 4096;
                    const float* wh2 = sw + 5120;
                    float ir = 0.f, iz = 0.f, inn = 0.f;
                    float hr = 0.f, hz = 0.f, hnn = 0.f;
#pragma unroll 2
                    for (int k = lane * 4; k < HID; k += 128) {
                        float4 x4 = *(const float4*)(s_x + k);
                        float4 h4 = *(const float4*)(s_h1 + k);
                        float4 a;
                        a = *(const float4*)(wi0 + k);
                        ir  += a.x * x4.x + a.y * x4.y + a.z * x4.z + a.w * x4.w;
                        a = *(const float4*)(wi1 + k);
                        iz  += a.x * x4.x + a.y * x4.y + a.z * x4.z + a.w * x4.w;
                        a = *(const float4*)(wi2 + k);
                        inn += a.x * x4.x + a.y * x4.y + a.z * x4.z + a.w * x4.w;
                        a = *(const float4*)(wh0 + k);
                        hr  += a.x * h4.x + a.y * h4.y + a.z * h4.z + a.w * h4.w;
                        a = *(const float4*)(wh1 + k);
                        hz  += a.x * h4.x + a.y * h4.y + a.z * h4.z + a.w * h4.w;
                        a = *(const float4*)(wh2 + k);
                        hnn += a.x * h4.x + a.y * h4.y + a.z * h4.z + a.w * h4.w;
                    }
                    ir = wredux(ir); iz = wredux(iz); inn = wredux(inn);
                    hr = wredux(hr); hz = wredux(hz); hnn = wredux(hnn);
                    if (lane == 0) {
                        int t = it - 1;
                        float gr = ir + bih1[j]           + hr + bhh1[j];
                        float gz = iz + bih1[HID + j]     + hz + bhh1[HID + j];
                        float gin = inn + bih1[2 * HID + j];
                        float ghn = hnn + bhh1[2 * HID + j];
                        float rr = sigmoidf_(gr);
                        float zz = sigmoidf_(gz);
                        float nn = tanhf(gin + rr * ghn);
                        float hv = (1.f - zz) * nn + zz * s_h1[j];
                        g_h1[phase][it][j] = hv;
                        if (phase) out[SCORES_SZ + t * 2048 + HID + j] = hv;
                    }
                }
            }
            grid_barrier(++epoch);
        }
    }
}

// ---------------------------------------------------------------------------
// Kernel 3: scores = dec_h1 @ out_W^T + out_b   -> out[0 .. 640000)
// ---------------------------------------------------------------------------
__global__ void scores_kernel(const float* __restrict__ outW,
                              const float* __restrict__ outb,
                              float* __restrict__ out) {
    __shared__ float ht[8][128];
    const int tid = threadIdx.x;
    const int vbase = blockIdx.x * 512 + tid;    // + i*128
    const int t0 = blockIdx.y * 8;

    int v[4];
    const float* w[4];
#pragma unroll
    for (int i = 0; i < 4; i++) {
        int vi = vbase + i * 128;
        v[i] = vi;
        int vc = (vi < VOCAB) ? vi : (VOCAB - 1);
        w[i] = outW + (size_t)vc * HID;
    }
    float acc[4][8];
#pragma unroll
    for (int i = 0; i < 4; i++)
#pragma unroll
        for (int tt = 0; tt < 8; tt++) acc[i][tt] = 0.f;

    for (int kc = 0; kc < HID; kc += 128) {
#pragma unroll
        for (int tt = 0; tt < 8; tt++)
            ht[tt][tid] = g_h1[1][t0 + tt + 1][kc + tid];
        __syncthreads();
#pragma unroll 4
        for (int k = 0; k < 128; k += 4) {
            float4 w4[4];
#pragma unroll
            for (int i = 0; i < 4; i++) w4[i] = *(const float4*)(w[i] + kc + k);
#pragma unroll
            for (int tt = 0; tt < 8; tt++) {
                float4 hv = *(const float4*)&ht[tt][k];
#pragma unroll
                for (int i = 0; i < 4; i++)
                    acc[i][tt] += w4[i].x * hv.x + w4[i].y * hv.y +
                                  w4[i].z * hv.z + w4[i].w * hv.w;
            }
        }
        __syncthreads();
    }
#pragma unroll
    for (int i = 0; i < 4; i++) {
        if (v[i] < VOCAB) {
            float bb = outb[v[i]];
#pragma unroll
            for (int tt = 0; tt < 8; tt++)
                out[(size_t)(t0 + tt) * VOCAB + v[i]] = acc[i][tt] + bb;
        }
    }
}

// ---------------------------------------------------------------------------
extern "C" void kernel_launch(void* const* d_in, const int* in_sizes, int n_in,
                              void* d_out, int out_size) {
    int p_emb = -1;
    for (int i = 0; i < n_in; i++) {
        if (in_sizes[i] == VOCAB * EMB) { p_emb = i; break; }
    }
    if (p_emb < 0) p_emb = 6;  // fallback: canonical order

    const int*   char_seq  = (const int*)d_in[0];
    const float* enc_state = (const float*)d_in[1];
    const int*   sos       = (const int*)d_in[2];
    const int*   target    = (const int*)d_in[p_emb - 1];
    const float* emb       = (const float*)d_in[p_emb];
    int wbase = p_emb + 1;
    const float* eWih0 = (const float*)d_in[wbase + 0];
    const float* eWhh0 = (const float*)d_in[wbase + 1];
    const float* eBih0 = (const float*)d_in[wbase + 2];
    const float* eBhh0 = (const float*)d_in[wbase + 3];
    const float* eWih1 = (const float*)d_in[wbase + 4];
    const float* eWhh1 = (const float*)d_in[wbase + 5];
    const float* eBih1 = (const float*)d_in[wbase + 6];
    const float* eBhh1 = (const float*)d_in[wbase + 7];
    const float* dWih0 = (const float*)d_in[wbase + 8];
    const float* dWhh0 = (const float*)d_in[wbase + 9];
    const float* dBih0 = (const float*)d_in[wbase + 10];
    const float* dBhh0 = (const float*)d_in[wbase + 11];
    const float* dWih1 = (const float*)d_in[wbase + 12];
    const float* dWhh1 = (const float*)d_in[wbase + 13];
    const float* dBih1 = (const float*)d_in[wbase + 14];
    const float* dBhh1 = (const float*)d_in[wbase + 15];
    const float* outW  = (const float*)d_in[wbase + 16];
    const float* outb  = (const float*)d_in[wbase + 17];
    float* out = (float*)d_out;
    (void)out_size;

    static int smem_set = 0;
    if (!smem_set) {
        cudaFuncSetAttribute(rec_kernel,
                             cudaFuncAttributeMaxDynamicSharedMemorySize,
                             SMEM_BYTES);
        smem_set = 1;
    }

    init_kernel<<<1, 256>>>(enc_state);

    rec_kernel<<<NB, NT, SMEM_BYTES>>>(eWih0, eBih0, eWhh0, eBhh0,
                                       eWih1, eBih1, eWhh1, eBhh1,
                                       dWih0, dBih0, dWhh0, dBhh0,
                                       dWih1, dBih1, dWhh1, dBhh1,
                                       char_seq, sos, target, emb, out);

    dim3 sg(20, 8);
    scores_kernel<<<sg, 128>>>(outW, outb, out);
}

// round 9
// speedup vs baseline: 2.2714x; 1.0426x over previous
#include <cuda_runtime.h>

#define VOCAB 10000
#define EMB   512
#define HID   1024
#define TSEQ  64
#define NB    128
#define NT    512
#define SCORES_SZ (TSEQ * VOCAB)

// dynamic smem layout (floats):
//  [0 .. 49152)        cell1 weights: 8 rows x 6 segs x 1024
//  [49152 .. 50176)    s_x   (HID)
//  [50176 .. 51200)    s_h1  (HID)
//  [51200 .. 51712)    s_e   (EMB)
#define SW1_F   (8 * 6 * 1024)
#define SMEM_FLOATS (SW1_F + HID + HID + EMB)
#define SMEM_BYTES  (SMEM_FLOATS * 4)

// Scratch (static __device__ arrays; no allocation allowed)
__device__ float g_h0[2][TSEQ + 1][HID];   // layer-0 hidden per step, [phase]
__device__ float g_h1[2][TSEQ + 1][HID];   // layer-1 hidden per step, [phase]
__device__ int   g_count;                  // barrier arrival counter (reset each launch)

// ---------------------------------------------------------------------------
// Kernel 1: init encoder hidden + reset barrier counter. 8 blocks so the copy
// isn't serialized on one SM (measured 7.7us at grid=1).
// ---------------------------------------------------------------------------
__global__ void init_kernel(const float* __restrict__ enc_state) {
    int i = blockIdx.x * 256 + threadIdx.x;
    if (i == 0) g_count = 0;
    if (i < HID)            g_h0[0][0][i] = enc_state[i];
    else if (i < 2 * HID)   g_h1[0][0][i - HID] = enc_state[i];
}

// ---------------------------------------------------------------------------
// Grid barrier: single counter; one red.release per block; only thread 0 polls.
// ---------------------------------------------------------------------------
__device__ __forceinline__ void grid_barrier(int epoch) {
    __syncthreads();
    if (threadIdx.x == 0) {
        asm volatile("red.release.gpu.global.add.s32 [%0], 1;"
                     :: "l"(&g_count) : "memory");
        int target = epoch * NB;
        int v;
        do {
            asm volatile("ld.acquire.gpu.global.b32 %0, [%1];"
                         : "=r"(v) : "l"(&g_count) : "memory");
        } while (v < target);
    }
    __syncthreads();
}

__device__ __forceinline__ float wredux(float v) {
    v += __shfl_xor_sync(0xffffffffu, v, 16);
    v += __shfl_xor_sync(0xffffffffu, v, 8);
    v += __shfl_xor_sync(0xffffffffu, v, 4);
    v += __shfl_xor_sync(0xffffffffu, v, 2);
    v += __shfl_xor_sync(0xffffffffu, v, 1);
    return v;
}

__device__ __forceinline__ float sigmoidf_(float x) {
    return 1.f / (1.f + expf(-x));
}

// ---------------------------------------------------------------------------
// Persistent recurrence kernel: 128 blocks x 512 threads.
// warps 0-7: layer-0 GRU step it (weights stream from L2, FULL unroll -> high
// MLP so the stream is BW-bound, not latency-bound);
// warps 8-15: layer-1 GRU step it-1 (weights SMEM-resident, loaded per phase).
// ---------------------------------------------------------------------------
__global__ void __launch_bounds__(NT, 1)
rec_kernel(const float* __restrict__ eWih0, const float* __restrict__ eBih0,
           const float* __restrict__ eWhh0, const float* __restrict__ eBhh0,
           const float* __restrict__ eWih1, const float* __restrict__ eBih1,
           const float* __restrict__ eWhh1, const float* __restrict__ eBhh1,
           const float* __restrict__ dWih0, const float* __restrict__ dBih0,
           const float* __restrict__ dWhh0, const float* __restrict__ dBhh0,
           const float* __restrict__ dWih1, const float* __restrict__ dBih1,
           const float* __restrict__ dWhh1, const float* __restrict__ dBhh1,
           const int* __restrict__ char_seq,
           const int* __restrict__ sos,
           const int* __restrict__ target,
           const float* __restrict__ emb,
           float* __restrict__ out) {
    extern __shared__ float smem[];
    float* s_w1 = smem;                    // [8][6][1024]
    float* s_x  = smem + SW1_F;            // [HID]
    float* s_h1 = s_x + HID;               // [HID]
    float* s_e  = s_h1 + HID;              // [EMB]

    const int tid  = threadIdx.x;
    const int wid  = tid >> 5;
    const int lane = tid & 31;
    const int bid  = blockIdx.x;
    const int sos0 = sos[0];
    int epoch = 0;

    for (int phase = 0; phase < 2; ++phase) {
        const float* Wih0 = phase ? dWih0 : eWih0;
        const float* bih0 = phase ? dBih0 : eBih0;
        const float* Whh0 = phase ? dWhh0 : eWhh0;
        const float* bhh0 = phase ? dBhh0 : eBhh0;
        const float* Wih1 = phase ? dWih1 : eWih1;
        const float* bih1 = phase ? dBih1 : eBih1;
        const float* Whh1 = phase ? dWhh1 : eWhh1;
        const float* bhh1 = phase ? dBhh1 : eBhh1;

        if (phase == 1) {
            // decoder init = encoder final hidden
            for (int i = bid * NT + tid; i < 2 * HID; i += NB * NT) {
                if (i < HID) g_h0[1][0][i] = g_h0[0][TSEQ][i];
                else         g_h1[1][0][i - HID] = g_h1[0][TSEQ][i - HID];
            }
            grid_barrier(++epoch);
        }

        // ---- load cell1 weights for this phase into smem ----
        {
            float4* dst = (float4*)s_w1;
            for (int idx = tid; idx < 8 * 6 * 256; idx += NT) {
                int row = idx / (6 * 256);
                int rem = idx % (6 * 256);
                int seg = rem / 256;
                int k4  = rem % 256;
                int j = (bid << 3) + row;          // global output row
                const float* src = (seg < 3)
                    ? (Wih1 + ((size_t)seg * HID + j) * HID)
                    : (Whh1 + ((size_t)(seg - 3) * HID + j) * HID);
                dst[idx] = *(const float4*)(src + k4 * 4);
            }
        }

        // preload embedding row for step 0 of this phase
        int id0 = (phase == 0) ? char_seq[0] : sos0;
        float pf = emb[(size_t)id0 * EMB + tid];

        for (int it = 0; it <= TSEQ; ++it) {
            // stage shared vectors (ordered before compute by __syncthreads)
            if (it < TSEQ) s_e[tid] = pf;
            for (int i = tid; i < HID; i += NT) s_x[i] = g_h0[phase][it][i];
            if (it >= 1)
                for (int i = tid; i < HID; i += NT) s_h1[i] = g_h1[phase][it - 1][i];
            __syncthreads();

            // prefetch next step's embedding row
            if (it + 1 < TSEQ) {
                int idn = (phase == 0) ? char_seq[it + 1] : target[it];
                pf = emb[(size_t)idn * EMB + tid];
            }

            if (wid < 8) {
                // ---- cell0: layer-0 GRU, step t = it (L2-streamed, full unroll) ----
                if (it < TSEQ) {
                    const int j = (bid << 3) + wid;
                    const float* w0 = Whh0 + (size_t)j * HID;
                    const float* w1 = w0 + (size_t)HID * HID;
                    const float* w2 = w1 + (size_t)HID * HID;
                    const float* u0 = Wih0 + (size_t)j * EMB;
                    const float* u1 = u0 + (size_t)HID * EMB;
                    const float* u2 = u1 + (size_t)HID * EMB;
                    float ar = 0.f, az = 0.f, an = 0.f, xn = 0.f;
#pragma unroll
                    for (int kk = 0; kk < 8; kk++) {
                        int k = lane * 4 + kk * 128;
                        float4 h4 = *(const float4*)(s_x + k);
                        float4 a = *(const float4*)(w0 + k);
                        float4 b = *(const float4*)(w1 + k);
                        float4 c = *(const float4*)(w2 + k);
                        ar += a.x * h4.x + a.y * h4.y + a.z * h4.z + a.w * h4.w;
                        az += b.x * h4.x + b.y * h4.y + b.z * h4.z + b.w * h4.w;
                        an += c.x * h4.x + c.y * h4.y + c.z * h4.z + c.w * h4.w;
                    }
#pragma unroll
                    for (int kk = 0; kk < 4; kk++) {
                        int k = lane * 4 + kk * 128;
                        float4 e4 = *(const float4*)(s_e + k);
                        float4 a = *(const float4*)(u0 + k);
                        float4 b = *(const float4*)(u1 + k);
                        float4 c = *(const float4*)(u2 + k);
                        ar += a.x * e4.x + a.y * e4.y + a.z * e4.z + a.w * e4.w;
                        az += b.x * e4.x + b.y * e4.y + b.z * e4.z + b.w * e4.w;
                        xn += c.x * e4.x + c.y * e4.y + c.z * e4.z + c.w * e4.w;
                    }
                    ar = wredux(ar); az = wredux(az);
                    an = wredux(an); xn = wredux(xn);
                    if (lane == 0) {
                        float gr = ar + bih0[j]       + bhh0[j];
                        float gz = az + bih0[HID + j] + bhh0[HID + j];
                        float gin = xn + bih0[2 * HID + j];
                        float ghn = an + bhh0[2 * HID + j];
                        float rr = sigmoidf_(gr);
                        float zz = sigmoidf_(gz);
                        float nn = tanhf(gin + rr * ghn);
                        float hv = (1.f - zz) * nn + zz * s_x[j];
                        g_h0[phase][it + 1][j] = hv;
                        if (phase) out[SCORES_SZ + it * 2048 + j] = hv;
                    }
                }
            } else {
                // ---- cell1: layer-1 GRU, step t = it-1 (SMEM weights) ----
                if (it >= 1) {
                    const int row = wid - 8;
                    const int j = (bid << 3) + row;
                    const float* sw = s_w1 + (size_t)row * 6 * 1024;
                    const float* wi0 = sw;
                    const float* wi1 = sw + 1024;
                    const float* wi2 = sw + 2048;
                    const float* wh0 = sw + 3072;
                    const float* wh1 = sw + 4096;
                    const float* wh2 = sw + 5120;
                    float ir = 0.f, iz = 0.f, inn = 0.f;
                    float hr = 0.f, hz = 0.f, hnn = 0.f;
#pragma unroll 2
                    for (int k = lane * 4; k < HID; k += 128) {
                        float4 x4 = *(const float4*)(s_x + k);
                        float4 h4 = *(const float4*)(s_h1 + k);
                        float4 a;
                        a = *(const float4*)(wi0 + k);
                        ir  += a.x * x4.x + a.y * x4.y + a.z * x4.z + a.w * x4.w;
                        a = *(const float4*)(wi1 + k);
                        iz  += a.x * x4.x + a.y * x4.y + a.z * x4.z + a.w * x4.w;
                        a = *(const float4*)(wi2 + k);
                        inn += a.x * x4.x + a.y * x4.y + a.z * x4.z + a.w * x4.w;
                        a = *(const float4*)(wh0 + k);
                        hr  += a.x * h4.x + a.y * h4.y + a.z * h4.z + a.w * h4.w;
                        a = *(const float4*)(wh1 + k);
                        hz  += a.x * h4.x + a.y * h4.y + a.z * h4.z + a.w * h4.w;
                        a = *(const float4*)(wh2 + k);
                        hnn += a.x * h4.x + a.y * h4.y + a.z * h4.z + a.w * h4.w;
                    }
                    ir = wredux(ir); iz = wredux(iz); inn = wredux(inn);
                    hr = wredux(hr); hz = wredux(hz); hnn = wredux(hnn);
                    if (lane == 0) {
                        int t = it - 1;
                        float gr = ir + bih1[j]           + hr + bhh1[j];
                        float gz = iz + bih1[HID + j]     + hz + bhh1[HID + j];
                        float gin = inn + bih1[2 * HID + j];
                        float ghn = hnn + bhh1[2 * HID + j];
                        float rr = sigmoidf_(gr);
                        float zz = sigmoidf_(gz);
                        float nn = tanhf(gin + rr * ghn);
                        float hv = (1.f - zz) * nn + zz * s_h1[j];
                        g_h1[phase][it][j] = hv;
                        if (phase) out[SCORES_SZ + t * 2048 + HID + j] = hv;
                    }
                }
            }
            grid_barrier(++epoch);
        }
    }
}

// ---------------------------------------------------------------------------
// Kernel 3: scores = dec_h1 @ out_W^T + out_b   -> out[0 .. 640000)
// ---------------------------------------------------------------------------
__global__ void scores_kernel(const float* __restrict__ outW,
                              const float* __restrict__ outb,
                              float* __restrict__ out) {
    __shared__ float ht[8][128];
    const int tid = threadIdx.x;
    const int vbase = blockIdx.x * 512 + tid;    // + i*128
    const int t0 = blockIdx.y * 8;

    int v[4];
    const float* w[4];
#pragma unroll
    for (int i = 0; i < 4; i++) {
        int vi = vbase + i * 128;
        v[i] = vi;
        int vc = (vi < VOCAB) ? vi : (VOCAB - 1);
        w[i] = outW + (size_t)vc * HID;
    }
    float acc[4][8];
#pragma unroll
    for (int i = 0; i < 4; i++)
#pragma unroll
        for (int tt = 0; tt < 8; tt++) acc[i][tt] = 0.f;

    for (int kc = 0; kc < HID; kc += 128) {
#pragma unroll
        for (int tt = 0; tt < 8; tt++)
            ht[tt][tid] = g_h1[1][t0 + tt + 1][kc + tid];
        __syncthreads();
#pragma unroll 4
        for (int k = 0; k < 128; k += 4) {
            float4 w4[4];
#pragma unroll
            for (int i = 0; i < 4; i++) w4[i] = *(const float4*)(w[i] + kc + k);
#pragma unroll
            for (int tt = 0; tt < 8; tt++) {
                float4 hv = *(const float4*)&ht[tt][k];
#pragma unroll
                for (int i = 0; i < 4; i++)
                    acc[i][tt] += w4[i].x * hv.x + w4[i].y * hv.y +
                                  w4[i].z * hv.z + w4[i].w * hv.w;
            }
        }
        __syncthreads();
    }
#pragma unroll
    for (int i = 0; i < 4; i++) {
        if (v[i] < VOCAB) {
            float bb = outb[v[i]];
#pragma unroll
            for (int tt = 0; tt < 8; tt++)
                out[(size_t)(t0 + tt) * VOCAB + v[i]] = acc[i][tt] + bb;
        }
    }
}

// ---------------------------------------------------------------------------
extern "C" void kernel_launch(void* const* d_in, const int* in_sizes, int n_in,
                              void* d_out, int out_size) {
    int p_emb = -1;
    for (int i = 0; i < n_in; i++) {
        if (in_sizes[i] == VOCAB * EMB) { p_emb = i; break; }
    }
    if (p_emb < 0) p_emb = 6;  // fallback: canonical order

    const int*   char_seq  = (const int*)d_in[0];
    const float* enc_state = (const float*)d_in[1];
    const int*   sos       = (const int*)d_in[2];
    const int*   target    = (const int*)d_in[p_emb - 1];
    const float* emb       = (const float*)d_in[p_emb];
    int wbase = p_emb + 1;
    const float* eWih0 = (const float*)d_in[wbase + 0];
    const float* eWhh0 = (const float*)d_in[wbase + 1];
    const float* eBih0 = (const float*)d_in[wbase + 2];
    const float* eBhh0 = (const float*)d_in[wbase + 3];
    const float* eWih1 = (const float*)d_in[wbase + 4];
    const float* eWhh1 = (const float*)d_in[wbase + 5];
    const float* eBih1 = (const float*)d_in[wbase + 6];
    const float* eBhh1 = (const float*)d_in[wbase + 7];
    const float* dWih0 = (const float*)d_in[wbase + 8];
    const float* dWhh0 = (const float*)d_in[wbase + 9];
    const float* dBih0 = (const float*)d_in[wbase + 10];
    const float* dBhh0 = (const float*)d_in[wbase + 11];
    const float* dWih1 = (const float*)d_in[wbase + 12];
    const float* dWhh1 = (const float*)d_in[wbase + 13];
    const float* dBih1 = (const float*)d_in[wbase + 14];
    const float* dBhh1 = (const float*)d_in[wbase + 15];
    const float* outW  = (const float*)d_in[wbase + 16];
    const float* outb  = (const float*)d_in[wbase + 17];
    float* out = (float*)d_out;
    (void)out_size;

    static int smem_set = 0;
    if (!smem_set) {
        cudaFuncSetAttribute(rec_kernel,
                             cudaFuncAttributeMaxDynamicSharedMemorySize,
                             SMEM_BYTES);
        smem_set = 1;
    }

    init_kernel<<<8, 256>>>(enc_state);

    rec_kernel<<<NB, NT, SMEM_BYTES>>>(eWih0, eBih0, eWhh0, eBhh0,
                                       eWih1, eBih1, eWhh1, eBhh1,
                                       dWih0, dBih0, dWhh0, dBhh0,
                                       dWih1, dBih1, dWhh1, dBhh1,
                                       char_seq, sos, target, emb, out);

    dim3 sg(20, 8);
    scores_kernel<<<sg, 128>>>(outW, outb, out);
}

// round 11
// speedup vs baseline: 2.6182x; 1.1527x over previous
#include <cuda_runtime.h>
#include <cuda_fp16.h>

#define VOCAB 10000
#define EMB   512
#define HID   1024
#define TSEQ  64
#define NB    128
#define NT    512
#define SCORES_SZ (TSEQ * VOCAB)

// per-row half counts
#define W0_ROW 4608            // 3*1024 (hh) + 3*512 (ih)
#define W1_ROW 6144            // 6*1024
#define SW0_H  (8 * W0_ROW)    // 36864 halfs = 73728 B
#define SW1_H  (8 * W1_ROW)    // 49152 halfs = 98304 B
// smem: [w0 halfs][w1 halfs][s_x f32][s_h1 f32][s_e f32]
#define SMEM_BYTES (SW0_H * 2 + SW1_H * 2 + (HID + HID + EMB) * 4)  // 182272

__device__ float g_h0[2][TSEQ + 1][HID];
__device__ float g_h1[2][TSEQ + 1][HID];
__device__ int   g_count;

// ---------------------------------------------------------------------------
__global__ void init_kernel(const float* __restrict__ enc_state) {
    int i = blockIdx.x * 256 + threadIdx.x;
    if (i == 0) g_count = 0;
    if (i < HID)            g_h0[0][0][i] = enc_state[i];
    else if (i < 2 * HID)   g_h1[0][0][i - HID] = enc_state[i];
}

// ---------------------------------------------------------------------------
__device__ __forceinline__ void grid_barrier(int epoch) {
    __syncthreads();
    if (threadIdx.x == 0) {
        asm volatile("red.release.gpu.global.add.s32 [%0], 1;"
                     :: "l"(&g_count) : "memory");
        int target = epoch * NB;
        int v;
        do {
            asm volatile("ld.acquire.gpu.global.b32 %0, [%1];"
                         : "=r"(v) : "l"(&g_count) : "memory");
        } while (v < target);
    }
    __syncthreads();
}

__device__ __forceinline__ float wredux(float v) {
    v += __shfl_xor_sync(0xffffffffu, v, 16);
    v += __shfl_xor_sync(0xffffffffu, v, 8);
    v += __shfl_xor_sync(0xffffffffu, v, 4);
    v += __shfl_xor_sync(0xffffffffu, v, 2);
    v += __shfl_xor_sync(0xffffffffu, v, 1);
    return v;
}

__device__ __forceinline__ float sigmoidf_(float x) {
    return 1.f / (1.f + expf(-x));
}

// 4 halfs (conflict-free LDS.64) dotted with a float4, fp32 accumulate
__device__ __forceinline__ float dot4h(const __half* w, float4 xv) {
    uint2 u = *(const uint2*)w;
    __half2 h0 = *(const __half2*)&u.x;
    __half2 h1 = *(const __half2*)&u.y;
    float2 f0 = __half22float2(h0);
    float2 f1 = __half22float2(h1);
    return f0.x * xv.x + f0.y * xv.y + f1.x * xv.z + f1.y * xv.w;
}

// ---------------------------------------------------------------------------
// Persistent recurrence kernel: 128 blocks x 512 threads, ALL weights fp16 in
// SMEM (converted from fp32 once per phase). fp32 accumulation and gate math.
// warps 0-7: layer-0 step it; warps 8-15: layer-1 step it-1.
// ---------------------------------------------------------------------------
__global__ void __launch_bounds__(NT, 1)
rec_kernel(const float* __restrict__ eWih0, const float* __restrict__ eBih0,
           const float* __restrict__ eWhh0, const float* __restrict__ eBhh0,
           const float* __restrict__ eWih1, const float* __restrict__ eBih1,
           const float* __restrict__ eWhh1, const float* __restrict__ eBhh1,
           const float* __restrict__ dWih0, const float* __restrict__ dBih0,
           const float* __restrict__ dWhh0, const float* __restrict__ dBhh0,
           const float* __restrict__ dWih1, const float* __restrict__ dBih1,
           const float* __restrict__ dWhh1, const float* __restrict__ dBhh1,
           const int* __restrict__ char_seq,
           const int* __restrict__ sos,
           const int* __restrict__ target,
           const float* __restrict__ emb,
           float* __restrict__ out) {
    extern __shared__ char smem_raw[];
    __half* s_w0 = (__half*)smem_raw;                  // [8][4608]
    __half* s_w1 = s_w0 + SW0_H;                       // [8][6144]
    float*  s_x  = (float*)(s_w1 + SW1_H);             // [HID]
    float*  s_h1 = s_x + HID;                          // [HID]
    float*  s_e  = s_h1 + HID;                         // [EMB]

    const int tid  = threadIdx.x;
    const int wid  = tid >> 5;
    const int lane = tid & 31;
    const int bid  = blockIdx.x;
    const int sos0 = sos[0];
    int epoch = 0;

    for (int phase = 0; phase < 2; ++phase) {
        const float* Wih0 = phase ? dWih0 : eWih0;
        const float* bih0 = phase ? dBih0 : eBih0;
        const float* Whh0 = phase ? dWhh0 : eWhh0;
        const float* bhh0 = phase ? dBhh0 : eBhh0;
        const float* Wih1 = phase ? dWih1 : eWih1;
        const float* bih1 = phase ? dBih1 : eBih1;
        const float* Whh1 = phase ? dWhh1 : eWhh1;
        const float* bhh1 = phase ? dBhh1 : eBhh1;

        if (phase == 1) {
            for (int i = bid * NT + tid; i < 2 * HID; i += NB * NT) {
                if (i < HID) g_h0[1][0][i] = g_h0[0][TSEQ][i];
                else         g_h1[1][0][i - HID] = g_h1[0][TSEQ][i - HID];
            }
            grid_barrier(++epoch);
        }

        // ---- convert + load this block's 8 rows of ALL weights into smem ----
        // cell0 row layout (halfs): [hh0|hh1|hh2: 3*1024][ih0|ih1|ih2: 3*512]
        for (int idx = tid; idx < 8 * 1152; idx += NT) {
            int row = idx / 1152, rem = idx % 1152;
            int j = (bid << 3) + row;
            const float* src; int hoff;
            if (rem < 768) {
                int seg = rem >> 8, k4 = rem & 255;
                src = Whh0 + (size_t)(seg * HID + j) * HID + k4 * 4;
                hoff = seg * 1024 + k4 * 4;
            } else {
                int r2 = rem - 768;
                int seg = r2 >> 7, k4 = r2 & 127;
                src = Wih0 + (size_t)(seg * HID + j) * EMB + k4 * 4;
                hoff = 3072 + seg * 512 + k4 * 4;
            }
            float4 v = *(const float4*)src;
            __half2 a = __floats2half2_rn(v.x, v.y);
            __half2 b = __floats2half2_rn(v.z, v.w);
            uint2 p;
            p.x = *(unsigned int*)&a;
            p.y = *(unsigned int*)&b;
            *(uint2*)(s_w0 + row * W0_ROW + hoff) = p;
        }
        // cell1 row layout (halfs): [ih0|ih1|ih2|hh0|hh1|hh2: 6*1024]
        for (int idx = tid; idx < 8 * 1536; idx += NT) {
            int row = idx / 1536, rem = idx % 1536;
            int j = (bid << 3) + row;
            int seg = rem >> 8, k4 = rem & 255;
            const float* src = (seg < 3)
                ? Wih1 + (size_t)(seg * HID + j) * HID + k4 * 4
                : Whh1 + (size_t)((seg - 3) * HID + j) * HID + k4 * 4;
            float4 v = *(const float4*)src;
            __half2 a = __floats2half2_rn(v.x, v.y);
            __half2 b = __floats2half2_rn(v.z, v.w);
            uint2 p;
            p.x = *(unsigned int*)&a;
            p.y = *(unsigned int*)&b;
            *(uint2*)(s_w1 + row * W1_ROW + seg * 1024 + k4 * 4) = p;
        }

        int id0 = (phase == 0) ? char_seq[0] : sos0;
        float pf = emb[(size_t)id0 * EMB + tid];

        for (int it = 0; it <= TSEQ; ++it) {
            if (it < TSEQ) s_e[tid] = pf;
            for (int i = tid; i < HID; i += NT) s_x[i] = g_h0[phase][it][i];
            if (it >= 1)
                for (int i = tid; i < HID; i += NT) s_h1[i] = g_h1[phase][it - 1][i];
            __syncthreads();   // orders loader stores + staging before compute

            if (it + 1 < TSEQ) {
                int idn = (phase == 0) ? char_seq[it + 1] : target[it];
                pf = emb[(size_t)idn * EMB + tid];
            }

            if (wid < 8) {
                // ---- cell0: layer-0 GRU, step t = it ----
                if (it < TSEQ) {
                    const int j = (bid << 3) + wid;
                    const __half* wr = s_w0 + wid * W0_ROW;
                    float ar = 0.f, az = 0.f, an = 0.f, xn = 0.f;
#pragma unroll
                    for (int c = 0; c < 8; c++) {
                        int k = lane * 4 + c * 128;
                        float4 xv = *(const float4*)(s_x + k);
                        ar += dot4h(wr + k, xv);
                        az += dot4h(wr + 1024 + k, xv);
                        an += dot4h(wr + 2048 + k, xv);
                    }
#pragma unroll
                    for (int c = 0; c < 4; c++) {
                        int k = lane * 4 + c * 128;
                        float4 ev = *(const float4*)(s_e + k);
                        ar += dot4h(wr + 3072 + k, ev);
                        az += dot4h(wr + 3584 + k, ev);
                        xn += dot4h(wr + 4096 + k, ev);
                    }
                    ar = wredux(ar); az = wredux(az);
                    an = wredux(an); xn = wredux(xn);
                    if (lane == 0) {
                        float gr = ar + bih0[j]       + bhh0[j];
                        float gz = az + bih0[HID + j] + bhh0[HID + j];
                        float gin = xn + bih0[2 * HID + j];
                        float ghn = an + bhh0[2 * HID + j];
                        float rr = sigmoidf_(gr);
                        float zz = sigmoidf_(gz);
                        float nn = tanhf(gin + rr * ghn);
                        float hv = (1.f - zz) * nn + zz * s_x[j];
                        g_h0[phase][it + 1][j] = hv;
                        if (phase) out[SCORES_SZ + it * 2048 + j] = hv;
                    }
                }
            } else {
                // ---- cell1: layer-1 GRU, step t = it-1 ----
                if (it >= 1) {
                    const int row = wid - 8;
                    const int j = (bid << 3) + row;
                    const __half* wr = s_w1 + row * W1_ROW;
                    float ir = 0.f, iz = 0.f, inn = 0.f;
                    float hr = 0.f, hz = 0.f, hnn = 0.f;
#pragma unroll
                    for (int c = 0; c < 8; c++) {
                        int k = lane * 4 + c * 128;
                        float4 xv = *(const float4*)(s_x + k);
                        float4 hv = *(const float4*)(s_h1 + k);
                        ir  += dot4h(wr + k, xv);
                        iz  += dot4h(wr + 1024 + k, xv);
                        inn += dot4h(wr + 2048 + k, xv);
                        hr  += dot4h(wr + 3072 + k, hv);
                        hz  += dot4h(wr + 4096 + k, hv);
                        hnn += dot4h(wr + 5120 + k, hv);
                    }
                    ir = wredux(ir); iz = wredux(iz); inn = wredux(inn);
                    hr = wredux(hr); hz = wredux(hz); hnn = wredux(hnn);
                    if (lane == 0) {
                        int t = it - 1;
                        float gr = ir + bih1[j]           + hr + bhh1[j];
                        float gz = iz + bih1[HID + j]     + hz + bhh1[HID + j];
                        float gin = inn + bih1[2 * HID + j];
                        float ghn = hnn + bhh1[2 * HID + j];
                        float rr = sigmoidf_(gr);
                        float zz = sigmoidf_(gz);
                        float nn = tanhf(gin + rr * ghn);
                        float hv = (1.f - zz) * nn + zz * s_h1[j];
                        g_h1[phase][it][j] = hv;
                        if (phase) out[SCORES_SZ + t * 2048 + HID + j] = hv;
                    }
                }
            }
            grid_barrier(++epoch);
        }
    }
}

// ---------------------------------------------------------------------------
// Kernel 3: scores = dec_h1 @ out_W^T + out_b   -> out[0 .. 640000)
// ---------------------------------------------------------------------------
__global__ void scores_kernel(const float* __restrict__ outW,
                              const float* __restrict__ outb,
                              float* __restrict__ out) {
    __shared__ float ht[8][128];
    const int tid = threadIdx.x;
    const int vbase = blockIdx.x * 512 + tid;
    const int t0 = blockIdx.y * 8;

    int v[4];
    const float* w[4];
#pragma unroll
    for (int i = 0; i < 4; i++) {
        int vi = vbase + i * 128;
        v[i] = vi;
        int vc = (vi < VOCAB) ? vi : (VOCAB - 1);
        w[i] = outW + (size_t)vc * HID;
    }
    float acc[4][8];
#pragma unroll
    for (int i = 0; i < 4; i++)
#pragma unroll
        for (int tt = 0; tt < 8; tt++) acc[i][tt] = 0.f;

    for (int kc = 0; kc < HID; kc += 128) {
#pragma unroll
        for (int tt = 0; tt < 8; tt++)
            ht[tt][tid] = g_h1[1][t0 + tt + 1][kc + tid];
        __syncthreads();
#pragma unroll 4
        for (int k = 0; k < 128; k += 4) {
            float4 w4[4];
#pragma unroll
            for (int i = 0; i < 4; i++) w4[i] = *(const float4*)(w[i] + kc + k);
#pragma unroll
            for (int tt = 0; tt < 8; tt++) {
                float4 hv = *(const float4*)&ht[tt][k];
#pragma unroll
                for (int i = 0; i < 4; i++)
                    acc[i][tt] += w4[i].x * hv.x + w4[i].y * hv.y +
                                  w4[i].z * hv.z + w4[i].w * hv.w;
            }
        }
        __syncthreads();
    }
#pragma unroll
    for (int i = 0; i < 4; i++) {
        if (v[i] < VOCAB) {
            float bb = outb[v[i]];
#pragma unroll
            for (int tt = 0; tt < 8; tt++)
                out[(size_t)(t0 + tt) * VOCAB + v[i]] = acc[i][tt] + bb;
        }
    }
}

// ---------------------------------------------------------------------------
extern "C" void kernel_launch(void* const* d_in, const int* in_sizes, int n_in,
                              void* d_out, int out_size) {
    int p_emb = -1;
    for (int i = 0; i < n_in; i++) {
        if (in_sizes[i] == VOCAB * EMB) { p_emb = i; break; }
    }
    if (p_emb < 0) p_emb = 6;

    const int*   char_seq  = (const int*)d_in[0];
    const float* enc_state = (const float*)d_in[1];
    const int*   sos       = (const int*)d_in[2];
    const int*   target    = (const int*)d_in[p_emb - 1];
    const float* emb       = (const float*)d_in[p_emb];
    int wbase = p_emb + 1;
    const float* eWih0 = (const float*)d_in[wbase + 0];
    const float* eWhh0 = (const float*)d_in[wbase + 1];
    const float* eBih0 = (const float*)d_in[wbase + 2];
    const float* eBhh0 = (const float*)d_in[wbase + 3];
    const float* eWih1 = (const float*)d_in[wbase + 4];
    const float* eWhh1 = (const float*)d_in[wbase + 5];
    const float* eBih1 = (const float*)d_in[wbase + 6];
    const float* eBhh1 = (const float*)d_in[wbase + 7];
    const float* dWih0 = (const float*)d_in[wbase + 8];
    const float* dWhh0 = (const float*)d_in[wbase + 9];
    const float* dBih0 = (const float*)d_in[wbase + 10];
    const float* dBhh0 = (const float*)d_in[wbase + 11];
    const float* dWih1 = (const float*)d_in[wbase + 12];
    const float* dWhh1 = (const float*)d_in[wbase + 13];
    const float* dBih1 = (const float*)d_in[wbase + 14];
    const float* dBhh1 = (const float*)d_in[wbase + 15];
    const float* outW  = (const float*)d_in[wbase + 16];
    const float* outb  = (const float*)d_in[wbase + 17];
    float* out = (float*)d_out;
    (void)out_size;

    static int smem_set = 0;
    if (!smem_set) {
        cudaFuncSetAttribute(rec_kernel,
                             cudaFuncAttributeMaxDynamicSharedMemorySize,
                             SMEM_BYTES);
        smem_set = 1;
    }

    init_kernel<<<8, 256>>>(enc_state);

    rec_kernel<<<NB, NT, SMEM_BYTES>>>(eWih0, eBih0, eWhh0, eBhh0,
                                       eWih1, eBih1, eWhh1, eBhh1,
                                       dWih0, dBih0, dWhh0, dBhh0,
                                       dWih1, dBih1, dWhh1, dBhh1,
                                       char_seq, sos, target, emb, out);

    dim3 sg(20, 8);
    scores_kernel<<<sg, 128>>>(outW, outb, out);
}

// round 17
// speedup vs baseline: 2.8851x; 1.1020x over previous
#include <cuda_runtime.h>
#include <cuda_fp16.h>

#define VOCAB 10000
#define EMB   512
#define HID   1024
#define TSEQ  64
#define NB    128
#define NT    1024
#define SCORES_SZ (TSEQ * VOCAB)

// per-row half counts
#define W0_ROW 4608            // 3*1024 (hh) + 3*512 (ih)
#define W1_ROW 6144            // 6*1024
#define SW0_H  (8 * W0_ROW)    // 73728 B
#define SW1_H  (8 * W1_ROW)    // 98304 B
// smem: w0 + w1 + s_x + s_h1 + s_e + partials
#define SMEM_BYTES (SW0_H * 2 + SW1_H * 2 + (HID + HID + EMB) * 4 + (8*2*4 + 8*2*6) * 4)

__device__ float g_h0[2][TSEQ + 1][HID];
__device__ float g_h1[2][TSEQ + 1][HID];
__device__ int   g_count;

// ---------------------------------------------------------------------------
__global__ void init_kernel(const float* __restrict__ enc_state) {
    int i = blockIdx.x * 256 + threadIdx.x;
    if (i == 0) g_count = 0;
    if (i < HID)            g_h0[0][0][i] = enc_state[i];
    else if (i < 2 * HID)   g_h1[0][0][i - HID] = enc_state[i];
}

// ---------------------------------------------------------------------------
__device__ __forceinline__ void grid_barrier(int epoch) {
    __syncthreads();
    if (threadIdx.x == 0) {
        asm volatile("red.release.gpu.global.add.s32 [%0], 1;"
                     :: "l"(&g_count) : "memory");
        int target = epoch * NB;
        int v;
        do {
            asm volatile("ld.acquire.gpu.global.b32 %0, [%1];"
                         : "=r"(v) : "l"(&g_count) : "memory");
        } while (v < target);
    }
    __syncthreads();
}

__device__ __forceinline__ float wredux(float v) {
    v += __shfl_xor_sync(0xffffffffu, v, 16);
    v += __shfl_xor_sync(0xffffffffu, v, 8);
    v += __shfl_xor_sync(0xffffffffu, v, 4);
    v += __shfl_xor_sync(0xffffffffu, v, 2);
    v += __shfl_xor_sync(0xffffffffu, v, 1);
    return v;
}

__device__ __forceinline__ float sigmoidf_(float x) {
    return 1.f / (1.f + expf(-x));
}

// 8 fp16 weights (one LDS.128) dotted with 8 fp32 vector elements, fp32 accum
__device__ __forceinline__ float dot8h(const __half* w, const float* x) {
    uint4 u = *(const uint4*)w;
    float2 f0 = __half22float2(*(const __half2*)&u.x);
    float2 f1 = __half22float2(*(const __half2*)&u.y);
    float2 f2 = __half22float2(*(const __half2*)&u.z);
    float2 f3 = __half22float2(*(const __half2*)&u.w);
    float4 xa = *(const float4*)x;
    float4 xb = *(const float4*)(x + 4);
    return f0.x * xa.x + f0.y * xa.y + f1.x * xa.z + f1.y * xa.w
         + f2.x * xb.x + f2.y * xb.y + f3.x * xb.z + f3.y * xb.w;
}

// ---------------------------------------------------------------------------
// Persistent recurrence: 128 blocks x 1024 threads (8 warps/SMSP for latency
// hiding). Two warps per output row, each covering half of k; partial gate
// sums combined via smem by 16 finalize threads.
//   warps 0-15 : cell0 (layer-0, step it);   row = wid>>1, khalf = wid&1
//   warps 16-31: cell1 (layer-1, step it-1); row = (wid-16)>>1, khalf = (wid-16)&1
// ---------------------------------------------------------------------------
__global__ void __launch_bounds__(NT, 1)
rec_kernel(const float* __restrict__ eWih0, const float* __restrict__ eBih0,
           const float* __restrict__ eWhh0, const float* __restrict__ eBhh0,
           const float* __restrict__ eWih1, const float* __restrict__ eBih1,
           const float* __restrict__ eWhh1, const float* __restrict__ eBhh1,
           const float* __restrict__ dWih0, const float* __restrict__ dBih0,
           const float* __restrict__ dWhh0, const float* __restrict__ dBhh0,
           const float* __restrict__ dWih1, const float* __restrict__ dBih1,
           const float* __restrict__ dWhh1, const float* __restrict__ dBhh1,
           const int* __restrict__ char_seq,
           const int* __restrict__ sos,
           const int* __restrict__ target,
           const float* __restrict__ emb,
           float* __restrict__ out) {
    extern __shared__ char smem_raw[];
    __half* s_w0 = (__half*)smem_raw;                  // [8][4608]
    __half* s_w1 = s_w0 + SW0_H;                       // [8][6144]
    float*  s_x  = (float*)(s_w1 + SW1_H);             // [HID]
    float*  s_h1 = s_x + HID;                          // [HID]
    float*  s_e  = s_h1 + HID;                         // [EMB]
    float*  s_p0 = s_e + EMB;                          // [8][2][4]
    float*  s_p1 = s_p0 + 8 * 2 * 4;                   // [8][2][6]

    const int tid  = threadIdx.x;
    const int wid  = tid >> 5;
    const int lane = tid & 31;
    const int bid  = blockIdx.x;
    const int sos0 = sos[0];
    int epoch = 0;

    for (int phase = 0; phase < 2; ++phase) {
        const float* Wih0 = phase ? dWih0 : eWih0;
        const float* bih0 = phase ? dBih0 : eBih0;
        const float* Whh0 = phase ? dWhh0 : eWhh0;
        const float* bhh0 = phase ? dBhh0 : eBhh0;
        const float* Wih1 = phase ? dWih1 : eWih1;
        const float* bih1 = phase ? dBih1 : eBih1;
        const float* Whh1 = phase ? dWhh1 : eWhh1;
        const float* bhh1 = phase ? dBhh1 : eBhh1;

        if (phase == 1) {
            for (int i = bid * NT + tid; i < 2 * HID; i += NB * NT) {
                if (i < HID) g_h0[1][0][i] = g_h0[0][TSEQ][i];
                else         g_h1[1][0][i - HID] = g_h1[0][TSEQ][i - HID];
            }
            grid_barrier(++epoch);
        }

        // ---- convert + load this block's 8 rows of ALL weights into smem ----
        for (int idx = tid; idx < 8 * 1152; idx += NT) {
            int row = idx / 1152, rem = idx % 1152;
            int j = (bid << 3) + row;
            const float* src; int hoff;
            if (rem < 768) {
                int seg = rem >> 8, k4 = rem & 255;
                src = Whh0 + (size_t)(seg * HID + j) * HID + k4 * 4;
                hoff = seg * 1024 + k4 * 4;
            } else {
                int r2 = rem - 768;
                int seg = r2 >> 7, k4 = r2 & 127;
                src = Wih0 + (size_t)(seg * HID + j) * EMB + k4 * 4;
                hoff = 3072 + seg * 512 + k4 * 4;
            }
            float4 v = *(const float4*)src;
            __half2 a = __floats2half2_rn(v.x, v.y);
            __half2 b = __floats2half2_rn(v.z, v.w);
            uint2 p;
            p.x = *(unsigned int*)&a;
            p.y = *(unsigned int*)&b;
            *(uint2*)(s_w0 + row * W0_ROW + hoff) = p;
        }
        for (int idx = tid; idx < 8 * 1536; idx += NT) {
            int row = idx / 1536, rem = idx % 1536;
            int j = (bid << 3) + row;
            int seg = rem >> 8, k4 = rem & 255;
            const float* src = (seg < 3)
                ? Wih1 + (size_t)(seg * HID + j) * HID + k4 * 4
                : Whh1 + (size_t)((seg - 3) * HID + j) * HID + k4 * 4;
            float4 v = *(const float4*)src;
            __half2 a = __floats2half2_rn(v.x, v.y);
            __half2 b = __floats2half2_rn(v.z, v.w);
            uint2 p;
            p.x = *(unsigned int*)&a;
            p.y = *(unsigned int*)&b;
            *(uint2*)(s_w1 + row * W1_ROW + seg * 1024 + k4 * 4) = p;
        }

        // preload per-row biases into registers (combined where possible)
        float b0r = 0.f, b0z = 0.f, b0in = 0.f, b0hn = 0.f;
        float b1r = 0.f, b1z = 0.f, b1in = 0.f, b1hn = 0.f;
        if (tid < 8) {
            int j = (bid << 3) + tid;
            b0r  = bih0[j] + bhh0[j];
            b0z  = bih0[HID + j] + bhh0[HID + j];
            b0in = bih0[2 * HID + j];
            b0hn = bhh0[2 * HID + j];
        }
        if (tid >= 32 && tid < 40) {
            int j = (bid << 3) + (tid - 32);
            b1r  = bih1[j] + bhh1[j];
            b1z  = bih1[HID + j] + bhh1[HID + j];
            b1in = bih1[2 * HID + j];
            b1hn = bhh1[2 * HID + j];
        }

        int id0 = (phase == 0) ? char_seq[0] : sos0;
        float pf = (tid < EMB) ? emb[(size_t)id0 * EMB + tid] : 0.f;

        for (int it = 0; it <= TSEQ; ++it) {
            // stage shared vectors (1 element per thread)
            if (it < TSEQ && tid < EMB) s_e[tid] = pf;
            s_x[tid] = g_h0[phase][it][tid];
            if (it >= 1) s_h1[tid] = g_h1[phase][it - 1][tid];
            __syncthreads();

            if (it + 1 < TSEQ && tid < EMB) {
                int idn = (phase == 0) ? char_seq[it + 1] : target[it];
                pf = emb[(size_t)idn * EMB + tid];
            }

            if (wid < 16) {
                // ---- cell0 partials: row = wid>>1, k-half = wid&1 ----
                if (it < TSEQ) {
                    const int row = wid >> 1;
                    const int kh  = wid & 1;
                    const __half* wr = s_w0 + row * W0_ROW;
                    const int kb = kh * 512;
                    float ar = 0.f, az = 0.f, an = 0.f, xn = 0.f;
#pragma unroll
                    for (int c = 0; c < 2; c++) {
                        int k = kb + lane * 8 + c * 256;
                        ar += dot8h(wr + k, s_x + k);
                        az += dot8h(wr + 1024 + k, s_x + k);
                        an += dot8h(wr + 2048 + k, s_x + k);
                    }
                    {
                        int k = kh * 256 + lane * 8;
                        ar += dot8h(wr + 3072 + k, s_e + k);
                        az += dot8h(wr + 3584 + k, s_e + k);
                        xn += dot8h(wr + 4096 + k, s_e + k);
                    }
                    ar = wredux(ar); az = wredux(az);
                    an = wredux(an); xn = wredux(xn);
                    if (lane == 0) {
                        float* p = s_p0 + (row * 2 + kh) * 4;
                        p[0] = ar; p[1] = az; p[2] = an; p[3] = xn;
                    }
                }
            } else {
                // ---- cell1 partials: row = (wid-16)>>1, k-half = (wid-16)&1 ----
                if (it >= 1) {
                    const int w2 = wid - 16;
                    const int row = w2 >> 1;
                    const int kh  = w2 & 1;
                    const __half* wr = s_w1 + row * W1_ROW;
                    const int kb = kh * 512;
                    float ir = 0.f, iz = 0.f, inn = 0.f;
                    float hr = 0.f, hz = 0.f, hnn = 0.f;
#pragma unroll
                    for (int c = 0; c < 2; c++) {
                        int k = kb + lane * 8 + c * 256;
                        ir  += dot8h(wr + k, s_x + k);
                        iz  += dot8h(wr + 1024 + k, s_x + k);
                        inn += dot8h(wr + 2048 + k, s_x + k);
                        hr  += dot8h(wr + 3072 + k, s_h1 + k);
                        hz  += dot8h(wr + 4096 + k, s_h1 + k);
                        hnn += dot8h(wr + 5120 + k, s_h1 + k);
                    }
                    ir = wredux(ir); iz = wredux(iz); inn = wredux(inn);
                    hr = wredux(hr); hz = wredux(hz); hnn = wredux(hnn);
                    if (lane == 0) {
                        float* p = s_p1 + (row * 2 + kh) * 6;
                        p[0] = ir; p[1] = iz; p[2] = inn;
                        p[3] = hr; p[4] = hz; p[5] = hnn;
                    }
                }
            }
            __syncthreads();

            // ---- finalize: combine k-halves + gate math + publish ----
            if (it < TSEQ && tid < 8) {
                int j = (bid << 3) + tid;
                const float* pa = s_p0 + (tid * 2 + 0) * 4;
                const float* pb = s_p0 + (tid * 2 + 1) * 4;
                float ar = pa[0] + pb[0];
                float az = pa[1] + pb[1];
                float an = pa[2] + pb[2];
                float xn = pa[3] + pb[3];
                float rr = sigmoidf_(ar + b0r);
                float zz = sigmoidf_(az + b0z);
                float nn = tanhf(xn + b0in + rr * (an + b0hn));
                float hv = (1.f - zz) * nn + zz * s_x[j];
                g_h0[phase][it + 1][j] = hv;
                if (phase) out[SCORES_SZ + it * 2048 + j] = hv;
            }
            if (it >= 1 && tid >= 32 && tid < 40) {
                int r = tid - 32;
                int j = (bid << 3) + r;
                int t = it - 1;
                const float* pa = s_p1 + (r * 2 + 0) * 6;
                const float* pb = s_p1 + (r * 2 + 1) * 6;
                float ir = pa[0] + pb[0];
                float iz = pa[1] + pb[1];
                float inn = pa[2] + pb[2];
                float hr = pa[3] + pb[3];
                float hz = pa[4] + pb[4];
                float hnn = pa[5] + pb[5];
                float rr = sigmoidf_(ir + hr + b1r);
                float zz = sigmoidf_(iz + hz + b1z);
                float nn = tanhf(inn + b1in + rr * (hnn + b1hn));
                float hv = (1.f - zz) * nn + zz * s_h1[j];
                g_h1[phase][it][j] = hv;
                if (phase) out[SCORES_SZ + t * 2048 + HID + j] = hv;
            }
            grid_barrier(++epoch);
        }
    }
}

// ---------------------------------------------------------------------------
// Kernel 3: scores = dec_h1 @ out_W^T + out_b   -> out[0 .. 640000)
// ---------------------------------------------------------------------------
__global__ void scores_kernel(const float* __restrict__ outW,
                              const float* __restrict__ outb,
                              float* __restrict__ out) {
    __shared__ float ht[8][128];
    const int tid = threadIdx.x;
    const int vbase = blockIdx.x * 512 + tid;
    const int t0 = blockIdx.y * 8;

    int v[4];
    const float* w[4];
#pragma unroll
    for (int i = 0; i < 4; i++) {
        int vi = vbase + i * 128;
        v[i] = vi;
        int vc = (vi < VOCAB) ? vi : (VOCAB - 1);
        w[i] = outW + (size_t)vc * HID;
    }
    float acc[4][8];
#pragma unroll
    for (int i = 0; i < 4; i++)
#pragma unroll
        for (int tt = 0; tt < 8; tt++) acc[i][tt] = 0.f;

    for (int kc = 0; kc < HID; kc += 128) {
#pragma unroll
        for (int tt = 0; tt < 8; tt++)
            ht[tt][tid] = g_h1[1][t0 + tt + 1][kc + tid];
        __syncthreads();
#pragma unroll 4
        for (int k = 0; k < 128; k += 4) {
            float4 w4[4];
#pragma unroll
            for (int i = 0; i < 4; i++) w4[i] = *(const float4*)(w[i] + kc + k);
#pragma unroll
            for (int tt = 0; tt < 8; tt++) {
                float4 hv = *(const float4*)&ht[tt][k];
#pragma unroll
                for (int i = 0; i < 4; i++)
                    acc[i][tt] += w4[i].x * hv.x + w4[i].y * hv.y +
                                  w4[i].z * hv.z + w4[i].w * hv.w;
            }
        }
        __syncthreads();
    }
#pragma unroll
    for (int i = 0; i < 4; i++) {
        if (v[i] < VOCAB) {
            float bb = outb[v[i]];
#pragma unroll
            for (int tt = 0; tt < 8; tt++)
                out[(size_t)(t0 + tt) * VOCAB + v[i]] = acc[i][tt] + bb;
        }
    }
}

// ---------------------------------------------------------------------------
extern "C" void kernel_launch(void* const* d_in, const int* in_sizes, int n_in,
                              void* d_out, int out_size) {
    int p_emb = -1;
    for (int i = 0; i < n_in; i++) {
        if (in_sizes[i] == VOCAB * EMB) { p_emb = i; break; }
    }
    if (p_emb < 0) p_emb = 6;

    const int*   char_seq  = (const int*)d_in[0];
    const float* enc_state = (const float*)d_in[1];
    const int*   sos       = (const int*)d_in[2];
    const int*   target    = (const int*)d_in[p_emb - 1];
    const float* emb       = (const float*)d_in[p_emb];
    int wbase = p_emb + 1;
    const float* eWih0 = (const float*)d_in[wbase + 0];
    const float* eWhh0 = (const float*)d_in[wbase + 1];
    const float* eBih0 = (const float*)d_in[wbase + 2];
    const float* eBhh0 = (const float*)d_in[wbase + 3];
    const float* eWih1 = (const float*)d_in[wbase + 4];
    const float* eWhh1 = (const float*)d_in[wbase + 5];
    const float* eBih1 = (const float*)d_in[wbase + 6];
    const float* eBhh1 = (const float*)d_in[wbase + 7];
    const float* dWih0 = (const float*)d_in[wbase + 8];
    const float* dWhh0 = (const float*)d_in[wbase + 9];
    const float* dBih0 = (const float*)d_in[wbase + 10];
    const float* dBhh0 = (const float*)d_in[wbase + 11];
    const float* dWih1 = (const float*)d_in[wbase + 12];
    const float* dWhh1 = (const float*)d_in[wbase + 13];
    const float* dBih1 = (const float*)d_in[wbase + 14];
    const float* dBhh1 = (const float*)d_in[wbase + 15];
    const float* outW  = (const float*)d_in[wbase + 16];
    const float* outb  = (const float*)d_in[wbase + 17];
    float* out = (float*)d_out;
    (void)out_size;

    static int smem_set = 0;
    if (!smem_set) {
        cudaFuncSetAttribute(rec_kernel,
                             cudaFuncAttributeMaxDynamicSharedMemorySize,
                             SMEM_BYTES);
        smem_set = 1;
    }

    init_kernel<<<8, 256>>>(enc_state);

    rec_kernel<<<NB, NT, SMEM_BYTES>>>(eWih0, eBih0, eWhh0, eBhh0,
                                       eWih1, eBih1, eWhh1, eBhh1,
                                       dWih0, dBih0, dWhh0, dBhh0,
                                       dWih1, dBih1, dWhh1, dBhh1,
                                       char_seq, sos, target, emb, out);

    dim3 sg(20, 8);
    scores_kernel<<<sg, 128>>>(outW, outb, out);
}